// round 4
// baseline (speedup 1.0000x reference)
#include <cuda_runtime.h>

#define J   24
#define TPB 128

__global__ __launch_bounds__(TPB, 8) void fk_kernel(
    const float* __restrict__ angles,   // [B, 24]
    const float* __restrict__ Torg,     // [24, 4, 4] row-major
    const float* __restrict__ axes,     // [24, 3] unit axes
    float* __restrict__ out,            // [B, 75]
    int B)
{
    // Per-joint constants: 12 floats of T_origin (rows 0..2), then
    // ux,uy,uz, uxx,uyy,uzz, uxy,uxz,uyz (21 used, padded to 24).
    __shared__ float jc[J][24];
    // Double-buffered column-chunk staging: output col c -> chunk c/25,
    // buffer parity (c/25)&1, local col c%25. Row stride 25 (odd) ->
    // per-lane writes at fixed col hit distinct banks.
    __shared__ float sbuf[2][TPB][25];

    const int tid = threadIdx.x;

    if (tid < J) {
        const float* p = Torg + tid * 16;
        #pragma unroll
        for (int k = 0; k < 12; ++k) jc[tid][k] = p[k];
        float ux = axes[tid * 3 + 0];
        float uy = axes[tid * 3 + 1];
        float uz = axes[tid * 3 + 2];
        jc[tid][12] = ux;      jc[tid][13] = uy;      jc[tid][14] = uz;
        jc[tid][15] = ux * ux; jc[tid][16] = uy * uy; jc[tid][17] = uz * uz;
        jc[tid][18] = ux * uy; jc[tid][19] = ux * uz; jc[tid][20] = uy * uz;
    }

    const int b = blockIdx.x * TPB + tid;
    const bool active = (b < B);
    const float4* ap = reinterpret_cast<const float4*>(angles + (size_t)b * J);

    const int nvalid = min(TPB, B - blockIdx.x * TPB);
    float* gout = out + (size_t)blockIdx.x * TPB * 75;

    // Chain transform M (3x4), init identity.
    float m00 = 1.f, m01 = 0.f, m02 = 0.f, m03 = 0.f;
    float m10 = 0.f, m11 = 1.f, m12 = 0.f, m13 = 0.f;
    float m20 = 0.f, m21 = 0.f, m22 = 1.f, m23 = 0.f;

    __syncthreads();  // jc ready

    if (active) {  // base_pos -> cols 0..2 (chunk 0, buf 0)
        sbuf[0][tid][0] = 0.f; sbuf[0][tid][1] = 0.f; sbuf[0][tid][2] = 0.f;
    }

    #pragma unroll
    for (int seg = 0; seg < 3; ++seg) {
        if (active) {
            // 8 angles for this segment via two LDG.128.
            float as[8];
            {
                float4 v0 = __ldg(ap + 2 * seg);
                float4 v1 = __ldg(ap + 2 * seg + 1);
                as[0] = v0.x; as[1] = v0.y; as[2] = v0.z; as[3] = v0.w;
                as[4] = v1.x; as[5] = v1.y; as[6] = v1.z; as[7] = v1.w;
            }
            #pragma unroll
            for (int jj = 0; jj < 8; ++jj) {
                const int j = 8 * seg + jj;
                const float* c = jc[j];
                const float p00 = c[0],  p01 = c[1],  p02 = c[2],  p03 = c[3];
                const float p10 = c[4],  p11 = c[5],  p12 = c[6],  p13 = c[7];
                const float p20 = c[8],  p21 = c[9],  p22 = c[10], p23 = c[11];

                // G = M * T_origin (affine)
                float g00 = m00 * p00 + m01 * p10 + m02 * p20;
                float g01 = m00 * p01 + m01 * p11 + m02 * p21;
                float g02 = m00 * p02 + m01 * p12 + m02 * p22;
                float g03 = m00 * p03 + m01 * p13 + m02 * p23 + m03;
                float g10 = m10 * p00 + m11 * p10 + m12 * p20;
                float g11 = m10 * p01 + m11 * p11 + m12 * p21;
                float g12 = m10 * p02 + m11 * p12 + m12 * p22;
                float g13 = m10 * p03 + m11 * p13 + m12 * p23 + m13;
                float g20 = m20 * p00 + m21 * p10 + m22 * p20;
                float g21 = m20 * p01 + m21 * p11 + m22 * p21;
                float g22 = m20 * p02 + m21 * p12 + m22 * p22;
                float g23 = m20 * p03 + m21 * p13 + m22 * p23 + m23;

                // Rodrigues: R = cos*I + (1-cos)*uu^T + sin*[u]x
                float s, co;
                __sincosf(as[jj], &s, &co);
                const float oc = 1.0f - co;
                const float ux = c[12], uy = c[13], uz = c[14];
                const float r00 = co + oc * c[15];
                const float r11 = co + oc * c[16];
                const float r22 = co + oc * c[17];
                const float oxy = oc * c[18], oxz = oc * c[19], oyz = oc * c[20];
                const float sux = s * ux, suy = s * uy, suz = s * uz;
                const float r01 = oxy - suz, r10 = oxy + suz;
                const float r02 = oxz + suy, r20 = oxz - suy;
                const float r12 = oyz - sux, r21 = oyz + sux;

                // M = G * Tj (rotation-only)
                m00 = g00 * r00 + g01 * r10 + g02 * r20;
                m01 = g00 * r01 + g01 * r11 + g02 * r21;
                m02 = g00 * r02 + g01 * r12 + g02 * r22;
                m10 = g10 * r00 + g11 * r10 + g12 * r20;
                m11 = g10 * r01 + g11 * r11 + g12 * r21;
                m12 = g10 * r02 + g11 * r12 + g12 * r22;
                m20 = g20 * r00 + g21 * r10 + g22 * r20;
                m21 = g20 * r01 + g21 * r11 + g22 * r21;
                m22 = g20 * r02 + g21 * r12 + g22 * r22;
                m03 = g03; m13 = g13; m23 = g23;

                // Stage position (compile-time column indices).
                const int c0 = 3 + 3 * j;
                sbuf[((c0 + 0) / 25) & 1][tid][(c0 + 0) % 25] = m03;
                sbuf[((c0 + 1) / 25) & 1][tid][(c0 + 1) % 25] = m13;
                sbuf[((c0 + 2) / 25) & 1][tid][(c0 + 2) % 25] = m23;
            }
        }

        __syncthreads();  // chunk `seg` fully staged

        // Flush chunk `seg` (cols [25*seg, 25*seg+25)) from buffer seg&1.
        {
            const float* sb = &sbuf[seg & 1][0][0];   // [TPB*25] linear
            float* g = gout + 25 * seg;
            const int cnt = nvalid * 25;
            #pragma unroll 5
            for (int i = tid; i < cnt; i += TPB) {
                const int r = i / 25;
                const int cc = i - r * 25;
                g[r * 75 + cc] = sb[i];
            }
        }

        __syncthreads();  // buffer reusable
    }
}

extern "C" void kernel_launch(void* const* d_in, const int* in_sizes, int n_in,
                              void* d_out, int out_size) {
    const float* angles = (const float*)d_in[0];   // [B, 24] float32
    const float* Torg   = (const float*)d_in[1];   // [24, 4, 4] float32
    const float* axes   = (const float*)d_in[2];   // [24, 3] float32
    float* out = (float*)d_out;                    // [B, 75] float32

    const int B = in_sizes[0] / J;
    const int blocks = (B + TPB - 1) / TPB;
    fk_kernel<<<blocks, TPB>>>(angles, Torg, axes, out, B);
}

// round 5
// speedup vs baseline: 1.1829x; 1.1829x over previous
#include <cuda_runtime.h>

#define J   24
#define TPB 128

// Joint constants in constant memory: fully-unrolled loop makes every access
// an immediate-offset const-bank operand that ptxas folds into FFMA directly.
__constant__ float cTorg[J * 16];   // [24,4,4] row-major
__constant__ float cAxes[J * 3];    // [24,3] unit axes

__global__ __launch_bounds__(TPB) void fk_kernel(
    const float* __restrict__ angles,   // [B, 24]
    float* __restrict__ out,            // [B, 75]
    int B)
{
    // Output staging: thread t owns s_out[t*75 .. t*75+74]. Stride 75 is odd
    // -> per-lane writes at fixed column are bank-conflict-free.
    __shared__ __align__(16) float s_out[TPB * 75];

    const int tid = threadIdx.x;
    const int b = blockIdx.x * TPB + tid;
    const bool active = (b < B);

    // All 24 angles via 6 LDG.128 (row start b*96 bytes is 16B aligned).
    float a[J];
    if (active) {
        const float4* ap = reinterpret_cast<const float4*>(angles + (size_t)b * J);
        #pragma unroll
        for (int q = 0; q < J / 4; ++q) {
            float4 v = __ldg(ap + q);
            a[4 * q + 0] = v.x; a[4 * q + 1] = v.y;
            a[4 * q + 2] = v.z; a[4 * q + 3] = v.w;
        }
    }

    if (active) {
        // Chain transform M (3x4), init identity.
        float m00 = 1.f, m01 = 0.f, m02 = 0.f, m03 = 0.f;
        float m10 = 0.f, m11 = 1.f, m12 = 0.f, m13 = 0.f;
        float m20 = 0.f, m21 = 0.f, m22 = 1.f, m23 = 0.f;

        float* so = s_out + tid * 75;
        so[0] = 0.f; so[1] = 0.f; so[2] = 0.f;   // base_pos

        #pragma unroll
        for (int j = 0; j < J; ++j) {
            // T_origin entries: const-bank operands (compile-time offsets).
            const float p00 = cTorg[j*16 + 0],  p01 = cTorg[j*16 + 1];
            const float p02 = cTorg[j*16 + 2],  p03 = cTorg[j*16 + 3];
            const float p10 = cTorg[j*16 + 4],  p11 = cTorg[j*16 + 5];
            const float p12 = cTorg[j*16 + 6],  p13 = cTorg[j*16 + 7];
            const float p20 = cTorg[j*16 + 8],  p21 = cTorg[j*16 + 9];
            const float p22 = cTorg[j*16 + 10], p23 = cTorg[j*16 + 11];

            // G = M * T_origin (affine 3x4 * 4x4-with-identity-bottom-row)
            float g00 = m00 * p00 + m01 * p10 + m02 * p20;
            float g01 = m00 * p01 + m01 * p11 + m02 * p21;
            float g02 = m00 * p02 + m01 * p12 + m02 * p22;
            float g03 = m00 * p03 + m01 * p13 + m02 * p23 + m03;
            float g10 = m10 * p00 + m11 * p10 + m12 * p20;
            float g11 = m10 * p01 + m11 * p11 + m12 * p21;
            float g12 = m10 * p02 + m11 * p12 + m12 * p22;
            float g13 = m10 * p03 + m11 * p13 + m12 * p23 + m13;
            float g20 = m20 * p00 + m21 * p10 + m22 * p20;
            float g21 = m20 * p01 + m21 * p11 + m22 * p21;
            float g22 = m20 * p02 + m21 * p12 + m22 * p22;
            float g23 = m20 * p03 + m21 * p13 + m22 * p23 + m23;

            // Rodrigues: R = cos*I + (1-cos)*uu^T + sin*[u]x
            // (== reference's I + A*K + Bc*K^2, K = skew(u*theta), |u|=1)
            float s, co;
            __sincosf(a[j], &s, &co);
            const float oc = 1.0f - co;
            const float ux = cAxes[j*3 + 0];
            const float uy = cAxes[j*3 + 1];
            const float uz = cAxes[j*3 + 2];
            const float tx = oc * ux, ty = oc * uy, tz = oc * uz;
            const float r00 = co + tx * ux;
            const float r11 = co + ty * uy;
            const float r22 = co + tz * uz;
            const float oxy = tx * uy, oxz = tx * uz, oyz = ty * uz;
            const float sux = s * ux, suy = s * uy, suz = s * uz;
            const float r01 = oxy - suz, r10 = oxy + suz;
            const float r02 = oxz + suy, r20 = oxz - suy;
            const float r12 = oyz - sux, r21 = oyz + sux;

            // M = G * Tj (rotation-only -> translation carries over)
            m00 = g00 * r00 + g01 * r10 + g02 * r20;
            m01 = g00 * r01 + g01 * r11 + g02 * r21;
            m02 = g00 * r02 + g01 * r12 + g02 * r22;
            m10 = g10 * r00 + g11 * r10 + g12 * r20;
            m11 = g10 * r01 + g11 * r11 + g12 * r21;
            m12 = g10 * r02 + g11 * r12 + g12 * r22;
            m20 = g20 * r00 + g21 * r10 + g22 * r20;
            m21 = g20 * r01 + g21 * r11 + g22 * r21;
            m22 = g20 * r02 + g21 * r12 + g22 * r22;
            m03 = g03; m13 = g13; m23 = g23;

            so[3 + 3 * j + 0] = m03;
            so[3 + 3 * j + 1] = m13;
            so[3 + 3 * j + 2] = m23;
        }
    }

    __syncthreads();  // s_out fully staged

    // Coalesced flush of the block's [TPB, 75] output slab.
    const int base = blockIdx.x * TPB;
    const int nvalid = min(TPB, B - base);
    float* gout = out + (size_t)base * 75;
    if (nvalid == TPB) {
        const float4* sv = reinterpret_cast<const float4*>(s_out);
        float4* gv = reinterpret_cast<float4*>(gout);
        #pragma unroll 5
        for (int i = tid; i < TPB * 75 / 4; i += TPB) gv[i] = sv[i];
    } else if (nvalid > 0) {
        const int cnt = nvalid * 75;
        for (int i = tid; i < cnt; i += TPB) gout[i] = s_out[i];
    }
}

extern "C" void kernel_launch(void* const* d_in, const int* in_sizes, int n_in,
                              void* d_out, int out_size) {
    const float* angles = (const float*)d_in[0];   // [B, 24] float32
    const float* Torg   = (const float*)d_in[1];   // [24, 4, 4] float32
    const float* axes   = (const float*)d_in[2];   // [24, 3] float32
    float* out = (float*)d_out;                    // [B, 75] float32

    // Async D2D copies into constant bank (graph-capturable memcpy nodes).
    cudaMemcpyToSymbolAsync(cTorg, Torg, J * 16 * sizeof(float), 0,
                            cudaMemcpyDeviceToDevice);
    cudaMemcpyToSymbolAsync(cAxes, axes, J * 3 * sizeof(float), 0,
                            cudaMemcpyDeviceToDevice);

    const int B = in_sizes[0] / J;
    const int blocks = (B + TPB - 1) / TPB;
    fk_kernel<<<blocks, TPB>>>(angles, out, B);
}